// round 16
// baseline (speedup 1.0000x reference)
#include <cuda_runtime.h>
#include <cstdint>

#define B_   16
#define C_   64
#define H_   80
#define W_   80
#define N_   32
#define HW_  (H_ * W_)
#define TOT_ (B_ * C_ * H_ * W_)

#define ASSIGN_BLOCKS (B_ * N_)           // 512
#define FOCAL_BLOCKS  1280
#define GRID_BLOCKS   (ASSIGN_BLOCKS + FOCAL_BLOCKS)   // 1792
#define N4_           (TOT_ / 4)          // 1,638,400 float4
#define FOCAL_CHUNK   (N4_ / FOCAL_BLOCKS) // 1280 float4 = 5 per thread exact
#define ASSIGN_ROUNDS (HW_ / 256)          // 25

static_assert(FOCAL_BLOCKS * FOCAL_CHUNK == N4_, "focal coverage");
static_assert(FOCAL_CHUNK == 5 * 256, "focal loads per thread");
static_assert(ASSIGN_ROUNDS * 256 == HW_, "assign coverage");

// Per-slot partials: every slot is written every run -> no zeroing needed.
__device__ unsigned g_match_p[ASSIGN_BLOCKS];
__device__ double   g_focal_part[FOCAL_BLOCKS];
__device__ double   g_pos_l1[B_];
__device__ double   g_pos_gi[B_];
__device__ double   g_pos_cf[B_];
__device__ int      g_pos_cnt[B_];
__device__ int      g_batch_done[B_];     // self-resetting
__device__ int      g_done = 0;           // self-resetting

// exact (reference-matching) GIoU — used only in the sparse pos phase
__device__ __forceinline__ float giou_f(float4 p, float4 q, float a2) {
    float a1 = (p.z - p.x) * (p.w - p.y);
    float ltx = fmaxf(p.x, q.x), lty = fmaxf(p.y, q.y);
    float rbx = fminf(p.z, q.z), rby = fminf(p.w, q.w);
    float wx = fmaxf(rbx - ltx, 0.0f), wy = fmaxf(rby - lty, 0.0f);
    float inter = wx * wy;
    float uni = a1 + a2 - inter;
    float iou = inter / uni;
    float ex = fminf(p.x, q.x), ey = fminf(p.y, q.y);
    float fx = fmaxf(p.z, q.z), fy = fmaxf(p.w, q.w);
    float ew = fmaxf(fx - ex, 0.0f), eh = fmaxf(fy - ey, 0.0f);
    float ae = ew * eh;
    return iou - (ae - uni) / ae;
}

// fast GIoU for the argmax scan: giou = inter/uni + uni/ae - 1,
// folded over the common denominator -> ONE __fdividef. (R10-verified.)
__device__ __forceinline__ float giou_fast(float4 p, float4 q, float a2) {
    float a1 = (p.z - p.x) * (p.w - p.y);
    float wx = fmaxf(fminf(p.z, q.z) - fmaxf(p.x, q.x), 0.0f);
    float wy = fmaxf(fminf(p.w, q.w) - fmaxf(p.y, q.y), 0.0f);
    float inter = wx * wy;
    float uni = a1 + a2 - inter;
    float ex = fmaxf(p.z, q.z) - fminf(p.x, q.x);
    float ey = fmaxf(p.w, q.w) - fminf(p.y, q.y);
    float ae = ex * ey;
    float den = uni * ae;
    float num = fmaf(uni, uni, fmaf(inter, ae, -den));
    return __fdividef(num, den);
}

__device__ __forceinline__ float block_reduce_sum(float v, float* sh32) {
    int lane = threadIdx.x & 31;
    int wid  = threadIdx.x >> 5;
    #pragma unroll
    for (int o = 16; o > 0; o >>= 1) v += __shfl_down_sync(0xffffffffu, v, o);
    if (lane == 0) sh32[wid] = v;
    __syncthreads();
    v = (threadIdx.x < (blockDim.x >> 5)) ? sh32[lane] : 0.0f;
    if (wid == 0) {
        #pragma unroll
        for (int o = 16; o > 0; o >>= 1) v += __shfl_down_sync(0xffffffffu, v, o);
    }
    return v;
}

__global__ void __launch_bounds__(256, 2)
fused_kernel(const float* __restrict__ pred,
             const float* __restrict__ conf,
             const float* __restrict__ gtb,
             const int*   __restrict__ gtl,
             float* __restrict__ out) {
    __shared__ float sv[256];
    __shared__ int   si[256];
    __shared__ float sh32[32];
    int tid = threadIdx.x;
    int bid = blockIdx.x;

    if (bid < ASSIGN_BLOCKS) {
        // ---------------- assignment for (b, g) ----------------
        int bg = bid;
        int b = bg >> 5;                  // N_ = 32
        int lab = gtl[bg];
        float4 gq = reinterpret_cast<const float4*>(gtb)[bg];
        float a2 = (gq.z - gq.x) * (gq.w - gq.y);
        const float4* pc = reinterpret_cast<const float4*>(pred)
                           + (size_t)(b * C_ + lab) * HW_;

        float best = -1e30f;
        int bidx = 0;
        // FULL unroll + 128-reg budget: ptxas can software-pipeline many
        // independent float4 loads (deep per-warp MLP).
        #pragma unroll
        for (int k = 0; k < ASSIGN_ROUNDS; k++) {
            int idx = k * 256 + tid;
            float v = giou_fast(pc[idx], gq, a2);
            if (v > best) { best = v; bidx = idx; }  // keeps smallest idx
        }
        sv[tid] = best;
        si[tid] = bidx;
        __syncthreads();
        for (int s = 128; s > 0; s >>= 1) {
            if (tid < s) {
                float v2 = sv[tid + s];
                int   i2 = si[tid + s];
                if (v2 > sv[tid] || (v2 == sv[tid] && i2 < si[tid])) {
                    sv[tid] = v2;
                    si[tid] = i2;
                }
            }
            __syncthreads();
        }

        // -------- store record, release, per-batch arrival --------
        __shared__ int batch_last;
        if (tid == 0) {
            int idx = si[0];
            int mi = idx / W_, mj = idx % W_;
            unsigned valid = (sv[0] > 0.3f) ? 1u : 0u;
            g_match_p[bg] = (valid << 30) | ((unsigned)lab << 16)
                          | ((unsigned)mi << 8) | (unsigned)mj;
            __threadfence();                       // release
            int t = atomicAdd(&g_batch_done[b], 1);
            batch_last = (t == N_ - 1) ? 1 : 0;
        }
        __syncthreads();

        if (batch_last) {
            __threadfence();   // acquire (one block per batch)
            __shared__ unsigned recs[N_];
            __shared__ float4   gbox[N_];
            if (tid < N_) {
                recs[tid] = ((volatile unsigned*)g_match_p)[b * N_ + tid];
                gbox[tid] = reinterpret_cast<const float4*>(gtb)[b * N_ + tid];
                if (tid == 0) g_batch_done[b] = 0;   // reset for next replay
            }
            __syncthreads();

            float sl1 = 0.0f, sgi = 0.0f, scf = 0.0f;
            int cnt = 0;
            #pragma unroll
            for (int half = 0; half < 2; half++) {
                int cell = (half << 8) + tid;       // 0..511
                int g = cell >> 4;
                int w = cell & 15;
                unsigned r = recs[g];
                int lab2 = (r >> 16) & 63;
                int mi  = (r >> 8) & 255;
                int mj  = r & 255;
                int i = mi - 2 + (w >> 2);
                int j = mj - 2 + (w & 3);
                bool act = ((r >> 30) & 1u) && ((unsigned)i < H_) && ((unsigned)j < W_);

                #pragma unroll
                for (int g2 = 0; g2 < N_; g2++) {
                    unsigned r2 = recs[g2];
                    int mi2 = (r2 >> 8) & 255;
                    int mj2 = r2 & 255;
                    bool cover = (g2 > g)
                               & (int)((r2 >> 30) & 1u)
                               & (((r2 ^ r) & 0x3F0000u) == 0u)
                               & ((unsigned)(i - mi2 + 2) < 4u)
                               & ((unsigned)(j - mj2 + 2) < 4u);
                    act &= !cover;
                }

                if (act) {
                    size_t off = (((size_t)b * C_ + lab2) * HW_ + (size_t)i * W_ + j);
                    float4 pb = reinterpret_cast<const float4*>(pred)[off];
                    float4 gq2 = gbox[g];
                    float a22 = (gq2.z - gq2.x) * (gq2.w - gq2.y);

                    sl1 += 0.25f * (fabsf(pb.x - gq2.x) + fabsf(pb.y - gq2.y) +
                                    fabsf(pb.z - gq2.z) + fabsf(pb.w - gq2.w));
                    sgi += 1.0f - giou_f(pb, gq2, a22);

                    float c = conf[off];
                    float p = fminf(fmaxf(c, 1e-6f), 1.0f - 1e-6f);
                    float f1 = 0.25f * (1.0f - p) * (1.0f - p) * (-__logf(p));
                    float f0 = 0.75f * p * p * (-__logf(1.0f - p));
                    scf += f1 - f0;
                    cnt += 1;
                }
            }

            float bl1 = block_reduce_sum(sl1, sh32);
            __syncthreads();
            float bgi = block_reduce_sum(sgi, sh32);
            __syncthreads();
            float bcf = block_reduce_sum(scf, sh32);
            __syncthreads();
            float bcnt = block_reduce_sum((float)cnt, sh32);
            if (tid == 0) {
                g_pos_l1[b]  = (double)bl1;
                g_pos_gi[b]  = (double)bgi;
                g_pos_cf[b]  = (double)bcf;
                g_pos_cnt[b] = (int)(bcnt + 0.5f);
            }
        }
    } else {
        // ---------------- dense focal (t = 0) partial ----------------
        // 0.75*p^2*(-ln(1-p)) = (-0.75*ln2) * p^2 * log2(1-p)
        const float KF = -0.51986038542f;   // -0.75 * ln(2)
        int fb = bid - ASSIGN_BLOCKS;
        const float4* c4 = reinterpret_cast<const float4*>(conf);
        int start = fb * FOCAL_CHUNK;

        float acc = 0.0f;
        #pragma unroll
        for (int k = 0; k < 5; k++) {
            float4 v = c4[start + k * 256 + tid];
            #pragma unroll
            for (int e = 0; e < 4; e++) {
                float c = (&v.x)[e];
                float p = fminf(fmaxf(c, 1e-6f), 1.0f - 1e-6f);
                float t = p * p * __log2f(1.0f - p);
                acc = fmaf(t, KF, acc);
            }
        }
        float bsum = block_reduce_sum(acc, sh32);
        if (tid == 0) g_focal_part[fb] = (double)bsum;
    }

    // ---------------- global last-block finalize ----------------
    __shared__ int is_last;
    __syncthreads();
    if (tid == 0) {
        __threadfence();                           // release
        int t = atomicAdd(&g_done, 1);
        is_last = (t == GRID_BLOCKS - 1) ? 1 : 0;
    }
    __syncthreads();
    if (!is_last) return;
    __threadfence();   // acquire (one block)

    double l1 = 0.0, gi = 0.0, cf = 0.0;
    int np = 0;
    for (int k = tid; k < FOCAL_BLOCKS; k += 256) cf += g_focal_part[k];
    if (tid < B_) {
        l1 = g_pos_l1[tid];
        gi = g_pos_gi[tid];
        cf += g_pos_cf[tid];
        np = g_pos_cnt[tid];
    }

    __shared__ double sd2[256];
    __shared__ int    sn2[256];
    sd2[tid] = l1; __syncthreads();
    for (int s = 128; s > 0; s >>= 1) { if (tid < s) sd2[tid] += sd2[tid + s]; __syncthreads(); }
    l1 = sd2[0]; __syncthreads();
    sd2[tid] = gi; __syncthreads();
    for (int s = 128; s > 0; s >>= 1) { if (tid < s) sd2[tid] += sd2[tid + s]; __syncthreads(); }
    gi = sd2[0]; __syncthreads();
    sd2[tid] = cf; __syncthreads();
    for (int s = 128; s > 0; s >>= 1) { if (tid < s) sd2[tid] += sd2[tid + s]; __syncthreads(); }
    cf = sd2[0]; __syncthreads();
    sn2[tid] = np; __syncthreads();
    for (int s = 128; s > 0; s >>= 1) { if (tid < s) sn2[tid] += sn2[tid + s]; __syncthreads(); }
    np = sn2[0];

    if (tid == 0) {
        float denom = (float)(np > 1 ? np : 1);
        float fl1 = (float)l1 / denom;
        float fgi = (float)gi / denom;
        float fcf = (float)(cf / (double)TOT_);
        out[0] = fl1;
        out[1] = fgi;
        out[2] = fcf;
        out[3] = fl1 + 2.0f * fgi + fcf;
        out[4] = (float)np / (float)TOT_;
        g_done = 0;   // reset for next replay
    }
}

extern "C" void kernel_launch(void* const* d_in, const int* in_sizes, int n_in,
                              void* d_out, int out_size) {
    const float* pred = (const float*)d_in[0];   // [B,C,H,W,4]
    const float* conf = (const float*)d_in[1];   // [B,C,H,W]
    // d_in[2] = cam (unused by the loss)
    const float* gtb  = (const float*)d_in[3];   // [B,N,4]
    const int*   gtl  = (const int*)d_in[4];     // [B,N]
    float* out = (float*)d_out;

    fused_kernel<<<GRID_BLOCKS, 256>>>(pred, conf, gtb, gtl, out);
}

// round 17
// speedup vs baseline: 1.1774x; 1.1774x over previous
#include <cuda_runtime.h>
#include <cstdint>

#define B_   16
#define C_   64
#define H_   80
#define W_   80
#define N_   32
#define HW_  (H_ * W_)
#define TOT_ (B_ * C_ * H_ * W_)

#define ASSIGN_BLOCKS (B_ * N_)           // 512
#define FOCAL_BLOCKS  640
#define GRID_BLOCKS   (ASSIGN_BLOCKS + FOCAL_BLOCKS)   // 1152
#define N4_           (TOT_ / 4)          // 1,638,400 float4
#define FOCAL_CHUNK   (N4_ / FOCAL_BLOCKS) // 2560 float4 = 10 per thread
#define ASSIGN_ROUNDS (HW_ / 256)          // 25
#define FOCAL_ROUNDS  (FOCAL_CHUNK / 256)  // 10

static_assert(FOCAL_BLOCKS * FOCAL_CHUNK == N4_, "focal coverage");
static_assert(FOCAL_ROUNDS * 256 == FOCAL_CHUNK, "focal loads per thread");
static_assert(ASSIGN_ROUNDS * 256 == HW_, "assign coverage");

// Per-slot partials: every slot is written every run -> no zeroing needed.
__device__ unsigned g_match_p[ASSIGN_BLOCKS];
__device__ double   g_focal_part[FOCAL_BLOCKS];
__device__ double   g_pos_l1[B_];
__device__ double   g_pos_gi[B_];
__device__ double   g_pos_cf[B_];
__device__ int      g_pos_cnt[B_];
__device__ int      g_batch_done[B_];     // self-resetting
__device__ int      g_done = 0;           // self-resetting

// exact (reference-matching) GIoU — used only in the sparse pos phase
__device__ __forceinline__ float giou_f(float4 p, float4 q, float a2) {
    float a1 = (p.z - p.x) * (p.w - p.y);
    float ltx = fmaxf(p.x, q.x), lty = fmaxf(p.y, q.y);
    float rbx = fminf(p.z, q.z), rby = fminf(p.w, q.w);
    float wx = fmaxf(rbx - ltx, 0.0f), wy = fmaxf(rby - lty, 0.0f);
    float inter = wx * wy;
    float uni = a1 + a2 - inter;
    float iou = inter / uni;
    float ex = fminf(p.x, q.x), ey = fminf(p.y, q.y);
    float fx = fmaxf(p.z, q.z), fy = fmaxf(p.w, q.w);
    float ew = fmaxf(fx - ex, 0.0f), eh = fmaxf(fy - ey, 0.0f);
    float ae = ew * eh;
    return iou - (ae - uni) / ae;
}

// fast GIoU for the argmax scan: giou = inter/uni + uni/ae - 1,
// folded over the common denominator -> ONE __fdividef. (R10-verified.)
__device__ __forceinline__ float giou_fast(float4 p, float4 q, float a2) {
    float a1 = (p.z - p.x) * (p.w - p.y);
    float wx = fmaxf(fminf(p.z, q.z) - fmaxf(p.x, q.x), 0.0f);
    float wy = fmaxf(fminf(p.w, q.w) - fmaxf(p.y, q.y), 0.0f);
    float inter = wx * wy;
    float uni = a1 + a2 - inter;
    float ex = fmaxf(p.z, q.z) - fminf(p.x, q.x);
    float ey = fmaxf(p.w, q.w) - fminf(p.y, q.y);
    float ae = ex * ey;
    float den = uni * ae;
    float num = fmaf(uni, uni, fmaf(inter, ae, -den));
    return __fdividef(num, den);
}

__device__ __forceinline__ float block_reduce_sum(float v, float* sh32) {
    int lane = threadIdx.x & 31;
    int wid  = threadIdx.x >> 5;
    #pragma unroll
    for (int o = 16; o > 0; o >>= 1) v += __shfl_down_sync(0xffffffffu, v, o);
    if (lane == 0) sh32[wid] = v;
    __syncthreads();
    v = (threadIdx.x < (blockDim.x >> 5)) ? sh32[lane] : 0.0f;
    if (wid == 0) {
        #pragma unroll
        for (int o = 16; o > 0; o >>= 1) v += __shfl_down_sync(0xffffffffu, v, o);
    }
    return v;
}

__global__ void fused_kernel(const float* __restrict__ pred,
                             const float* __restrict__ conf,
                             const float* __restrict__ gtb,
                             const int*   __restrict__ gtl,
                             float* __restrict__ out) {
    __shared__ float sv[256];
    __shared__ int   si[256];
    __shared__ float sh32[32];
    int tid = threadIdx.x;
    int bid = blockIdx.x;

    if (bid < ASSIGN_BLOCKS) {
        // ---------------- assignment for (b, g) ----------------
        int bg = bid;
        int b = bg >> 5;                  // N_ = 32
        int lab = gtl[bg];
        float4 gq = reinterpret_cast<const float4*>(gtb)[bg];
        float a2 = (gq.z - gq.x) * (gq.w - gq.y);
        const float4* pc = reinterpret_cast<const float4*>(pred)
                           + (size_t)(b * C_ + lab) * HW_;

        float best = -1e30f;
        int bidx = 0;
        // FULL unroll (R15-verified win): ptxas software-pipelines the
        // 25 independent float4 loads within the natural ~64-reg budget.
        #pragma unroll
        for (int k = 0; k < ASSIGN_ROUNDS; k++) {
            int idx = k * 256 + tid;
            float v = giou_fast(pc[idx], gq, a2);
            if (v > best) { best = v; bidx = idx; }  // keeps smallest idx
        }
        sv[tid] = best;
        si[tid] = bidx;
        __syncthreads();
        for (int s = 128; s > 0; s >>= 1) {
            if (tid < s) {
                float v2 = sv[tid + s];
                int   i2 = si[tid + s];
                if (v2 > sv[tid] || (v2 == sv[tid] && i2 < si[tid])) {
                    sv[tid] = v2;
                    si[tid] = i2;
                }
            }
            __syncthreads();
        }

        // -------- store record, release, per-batch arrival --------
        __shared__ int batch_last;
        if (tid == 0) {
            int idx = si[0];
            int mi = idx / W_, mj = idx % W_;
            unsigned valid = (sv[0] > 0.3f) ? 1u : 0u;
            g_match_p[bg] = (valid << 30) | ((unsigned)lab << 16)
                          | ((unsigned)mi << 8) | (unsigned)mj;
            __threadfence();                       // release
            int t = atomicAdd(&g_batch_done[b], 1);
            batch_last = (t == N_ - 1) ? 1 : 0;
        }
        __syncthreads();

        if (batch_last) {
            __threadfence();   // acquire (one block per batch)
            __shared__ unsigned recs[N_];
            __shared__ float4   gbox[N_];
            if (tid < N_) {
                recs[tid] = ((volatile unsigned*)g_match_p)[b * N_ + tid];
                gbox[tid] = reinterpret_cast<const float4*>(gtb)[b * N_ + tid];
                if (tid == 0) g_batch_done[b] = 0;   // reset for next replay
            }
            __syncthreads();

            float sl1 = 0.0f, sgi = 0.0f, scf = 0.0f;
            int cnt = 0;
            #pragma unroll
            for (int half = 0; half < 2; half++) {
                int cell = (half << 8) + tid;       // 0..511
                int g = cell >> 4;
                int w = cell & 15;
                unsigned r = recs[g];
                int lab2 = (r >> 16) & 63;
                int mi  = (r >> 8) & 255;
                int mj  = r & 255;
                int i = mi - 2 + (w >> 2);
                int j = mj - 2 + (w & 3);
                bool act = ((r >> 30) & 1u) && ((unsigned)i < H_) && ((unsigned)j < W_);

                #pragma unroll
                for (int g2 = 0; g2 < N_; g2++) {
                    unsigned r2 = recs[g2];
                    int mi2 = (r2 >> 8) & 255;
                    int mj2 = r2 & 255;
                    bool cover = (g2 > g)
                               & (int)((r2 >> 30) & 1u)
                               & (((r2 ^ r) & 0x3F0000u) == 0u)
                               & ((unsigned)(i - mi2 + 2) < 4u)
                               & ((unsigned)(j - mj2 + 2) < 4u);
                    act &= !cover;
                }

                if (act) {
                    size_t off = (((size_t)b * C_ + lab2) * HW_ + (size_t)i * W_ + j);
                    float4 pb = reinterpret_cast<const float4*>(pred)[off];
                    float4 gq2 = gbox[g];
                    float a22 = (gq2.z - gq2.x) * (gq2.w - gq2.y);

                    sl1 += 0.25f * (fabsf(pb.x - gq2.x) + fabsf(pb.y - gq2.y) +
                                    fabsf(pb.z - gq2.z) + fabsf(pb.w - gq2.w));
                    sgi += 1.0f - giou_f(pb, gq2, a22);

                    float c = conf[off];
                    float p = fminf(fmaxf(c, 1e-6f), 1.0f - 1e-6f);
                    float f1 = 0.25f * (1.0f - p) * (1.0f - p) * (-__logf(p));
                    float f0 = 0.75f * p * p * (-__logf(1.0f - p));
                    scf += f1 - f0;
                    cnt += 1;
                }
            }

            float bl1 = block_reduce_sum(sl1, sh32);
            __syncthreads();
            float bgi = block_reduce_sum(sgi, sh32);
            __syncthreads();
            float bcf = block_reduce_sum(scf, sh32);
            __syncthreads();
            float bcnt = block_reduce_sum((float)cnt, sh32);
            if (tid == 0) {
                g_pos_l1[b]  = (double)bl1;
                g_pos_gi[b]  = (double)bgi;
                g_pos_cf[b]  = (double)bcf;
                g_pos_cnt[b] = (int)(bcnt + 0.5f);
            }
        }
    } else {
        // ---------------- dense focal (t = 0) partial ----------------
        // 0.75*p^2*(-ln(1-p)) = (-0.75*ln2) * p^2 * log2(1-p)
        // 10 independent float4 loads per thread, fully unrolled (deep MLP).
        const float KF = -0.51986038542f;   // -0.75 * ln(2)
        int fb = bid - ASSIGN_BLOCKS;
        const float4* c4 = reinterpret_cast<const float4*>(conf);
        int start = fb * FOCAL_CHUNK;

        float acc = 0.0f;
        #pragma unroll
        for (int k = 0; k < FOCAL_ROUNDS; k++) {
            float4 v = c4[start + k * 256 + tid];
            #pragma unroll
            for (int e = 0; e < 4; e++) {
                float c = (&v.x)[e];
                float p = fminf(fmaxf(c, 1e-6f), 1.0f - 1e-6f);
                float t = p * p * __log2f(1.0f - p);
                acc = fmaf(t, KF, acc);
            }
        }
        float bsum = block_reduce_sum(acc, sh32);
        if (tid == 0) g_focal_part[fb] = (double)bsum;
    }

    // ---------------- global last-block finalize ----------------
    __shared__ int is_last;
    __syncthreads();
    if (tid == 0) {
        __threadfence();                           // release
        int t = atomicAdd(&g_done, 1);
        is_last = (t == GRID_BLOCKS - 1) ? 1 : 0;
    }
    __syncthreads();
    if (!is_last) return;
    __threadfence();   // acquire (one block)

    double l1 = 0.0, gi = 0.0, cf = 0.0;
    int np = 0;
    for (int k = tid; k < FOCAL_BLOCKS; k += 256) cf += g_focal_part[k];
    if (tid < B_) {
        l1 = g_pos_l1[tid];
        gi = g_pos_gi[tid];
        cf += g_pos_cf[tid];
        np = g_pos_cnt[tid];
    }

    __shared__ double sd2[256];
    __shared__ int    sn2[256];
    sd2[tid] = l1; __syncthreads();
    for (int s = 128; s > 0; s >>= 1) { if (tid < s) sd2[tid] += sd2[tid + s]; __syncthreads(); }
    l1 = sd2[0]; __syncthreads();
    sd2[tid] = gi; __syncthreads();
    for (int s = 128; s > 0; s >>= 1) { if (tid < s) sd2[tid] += sd2[tid + s]; __syncthreads(); }
    gi = sd2[0]; __syncthreads();
    sd2[tid] = cf; __syncthreads();
    for (int s = 128; s > 0; s >>= 1) { if (tid < s) sd2[tid] += sd2[tid + s]; __syncthreads(); }
    cf = sd2[0]; __syncthreads();
    sn2[tid] = np; __syncthreads();
    for (int s = 128; s > 0; s >>= 1) { if (tid < s) sn2[tid] += sn2[tid + s]; __syncthreads(); }
    np = sn2[0];

    if (tid == 0) {
        float denom = (float)(np > 1 ? np : 1);
        float fl1 = (float)l1 / denom;
        float fgi = (float)gi / denom;
        float fcf = (float)(cf / (double)TOT_);
        out[0] = fl1;
        out[1] = fgi;
        out[2] = fcf;
        out[3] = fl1 + 2.0f * fgi + fcf;
        out[4] = (float)np / (float)TOT_;
        g_done = 0;   // reset for next replay
    }
}

extern "C" void kernel_launch(void* const* d_in, const int* in_sizes, int n_in,
                              void* d_out, int out_size) {
    const float* pred = (const float*)d_in[0];   // [B,C,H,W,4]
    const float* conf = (const float*)d_in[1];   // [B,C,H,W]
    // d_in[2] = cam (unused by the loss)
    const float* gtb  = (const float*)d_in[3];   // [B,N,4]
    const int*   gtl  = (const int*)d_in[4];     // [B,N]
    float* out = (float*)d_out;

    fused_kernel<<<GRID_BLOCKS, 256>>>(pred, conf, gtb, gtl, out);
}